// round 1
// baseline (speedup 1.0000x reference)
#include <cuda_runtime.h>
#include <math.h>

#define HIDDEN 512
#define NHEADS 8
#define HDIM   64
#define BATCH  2
#define SEQ    2048
#define M_TOT  (BATCH*SEQ)      // 4096
#define N_TOT  (3*HIDDEN)       // 1536
#define K_TOT  HIDDEN           // 512

// Scratch: Q/K/V in [B,H,S,d] layout (8 MB each). Temperature folded into Q.
__device__ float g_Q[BATCH*NHEADS*SEQ*HDIM];
__device__ float g_K[BATCH*NHEADS*SEQ*HDIM];
__device__ float g_V[BATCH*NHEADS*SEQ*HDIM];

// ---------------------------------------------------------------------------
// QKV GEMM: out[m][n] = sum_k x[m][k] * W[n][k], scattered to g_Q/g_K/g_V
// ---------------------------------------------------------------------------
#define BM 64
#define BN 64
#define BK 16
#define GP 68   // smem pitch (floats), 16B aligned rows

__global__ __launch_bounds__(256) void qkv_gemm_kernel(
    const float* __restrict__ x, const float* __restrict__ W)
{
    __shared__ float As[BK][GP];   // As[k][m]
    __shared__ float Bs[BK][GP];   // Bs[k][n]

    const int tid = threadIdx.x;
    const int tx = tid & 15;       // 0..15 -> n sub
    const int ty = tid >> 4;       // 0..15 -> m sub
    const int m0 = blockIdx.x * BM;
    const int n0 = blockIdx.y * BN;

    const int lr = tid >> 2;          // 0..63 row within tile
    const int lk = (tid & 3) * 4;     // 0,4,8,12 k within tile

    float acc[4][4] = {};

    for (int k0 = 0; k0 < K_TOT; k0 += BK) {
        float4 a4 = *(const float4*)&x[(m0 + lr) * K_TOT + k0 + lk];
        float4 b4 = *(const float4*)&W[(n0 + lr) * K_TOT + k0 + lk];
        __syncthreads();
        As[lk+0][lr] = a4.x; As[lk+1][lr] = a4.y;
        As[lk+2][lr] = a4.z; As[lk+3][lr] = a4.w;
        Bs[lk+0][lr] = b4.x; Bs[lk+1][lr] = b4.y;
        Bs[lk+2][lr] = b4.z; Bs[lk+3][lr] = b4.w;
        __syncthreads();
        #pragma unroll
        for (int kk = 0; kk < BK; kk++) {
            float4 av = *(float4*)&As[kk][ty*4];
            float4 bv = *(float4*)&Bs[kk][tx*4];
            acc[0][0] += av.x*bv.x; acc[0][1] += av.x*bv.y;
            acc[0][2] += av.x*bv.z; acc[0][3] += av.x*bv.w;
            acc[1][0] += av.y*bv.x; acc[1][1] += av.y*bv.y;
            acc[1][2] += av.y*bv.z; acc[1][3] += av.y*bv.w;
            acc[2][0] += av.z*bv.x; acc[2][1] += av.z*bv.y;
            acc[2][2] += av.z*bv.z; acc[2][3] += av.z*bv.w;
            acc[3][0] += av.w*bv.x; acc[3][1] += av.w*bv.y;
            acc[3][2] += av.w*bv.z; acc[3][3] += av.w*bv.w;
        }
    }

    // Epilogue: n -> (head h, which in {Q,K,V}, dd). Block's 64 n-columns lie
    // in ONE 64-wide segment (n0 is 64-aligned, segments are 64-aligned).
    const int n = n0 + tx*4;          // j=0 column; j=0..3 are consecutive dd
    const int h     = n / (3*HDIM);
    const int rr    = n % (3*HDIM);
    const int which = rr / HDIM;
    const int dd    = rr % HDIM;
    const float scale = (which == 0) ? 0.125f : 1.0f;  // 1/sqrt(64)
    float* dst = (which == 0) ? g_Q : (which == 1) ? g_K : g_V;

    #pragma unroll
    for (int i = 0; i < 4; i++) {
        const int m = m0 + ty*4 + i;
        const int b = m / SEQ, s = m % SEQ;
        float4 r4 = make_float4(acc[i][0]*scale, acc[i][1]*scale,
                                acc[i][2]*scale, acc[i][3]*scale);
        *(float4*)&dst[(((b*NHEADS + h)*SEQ) + s)*HDIM + dd] = r4;
    }
}

// ---------------------------------------------------------------------------
// Flash attention: per (b,h) pair, Q tile = 64 rows, KV tile = 64.
// Qs[k][r], Ks[k][c] (k-major), Vs[c][d] (natural), Ps[c][r] (transposed).
// All inner-loop smem reads are conflict-free/broadcast LDS.128.
// ---------------------------------------------------------------------------
#define AP 68
#define ATTN_SMEM (4*64*AP*4)   // 69632 bytes

__global__ __launch_bounds__(256) void attn_kernel(float* __restrict__ out)
{
    extern __shared__ float sm[];
    float* Qs = sm;               // [64][AP]  Qs[k][r]
    float* Ks = sm + 64*AP;       // [64][AP]  Ks[k][c]
    float* Vs = sm + 2*64*AP;     // [64][AP]  Vs[c][d]
    float* Ps = sm + 3*64*AP;     // [64][AP]  Ps[c][r]

    const int tid = threadIdx.x;
    const int tx = tid & 15;      // score-col / out-dim group
    const int ty = tid >> 4;      // score-row group
    const int bh = blockIdx.y;    // 0..15  (b*8+h)
    const int q0 = blockIdx.x * 64;

    const float* Qg = g_Q + bh * (SEQ*HDIM) + q0*HDIM;
    const float* Kg = g_K + bh * (SEQ*HDIM);
    const float* Vg = g_V + bh * (SEQ*HDIM);

    const int lr = tid >> 2;          // 0..63
    const int lkb = (tid & 3) * 4;    // 0,4,8,12

    // Load Q tile transposed into Qs[k][r]
    #pragma unroll
    for (int u = 0; u < 4; u++) {
        int k = lkb + u*16;
        float4 v = *(const float4*)&Qg[lr*HDIM + k];
        Qs[(k+0)*AP + lr] = v.x; Qs[(k+1)*AP + lr] = v.y;
        Qs[(k+2)*AP + lr] = v.z; Qs[(k+3)*AP + lr] = v.w;
    }

    float o[4][4] = {};
    float mrow[4] = {-INFINITY, -INFINITY, -INFINITY, -INFINITY};
    float lrow[4] = {};

    for (int kt = 0; kt < SEQ; kt += 64) {
        // Load K tile (transposed) and V tile (natural)
        #pragma unroll
        for (int u = 0; u < 4; u++) {
            int k = lkb + u*16;
            float4 kv = *(const float4*)&Kg[(kt + lr)*HDIM + k];
            Ks[(k+0)*AP + lr] = kv.x; Ks[(k+1)*AP + lr] = kv.y;
            Ks[(k+2)*AP + lr] = kv.z; Ks[(k+3)*AP + lr] = kv.w;
            float4 vv = *(const float4*)&Vg[(kt + lr)*HDIM + k];
            *(float4*)&Vs[lr*AP + k] = vv;
        }
        __syncthreads();   // K/V (and first-iter Q) visible

        // Scores: sc[i][j] = sum_k Q[r][k]*K[c][k]  (temperature already in Q)
        float sc[4][4] = {};
        #pragma unroll 4
        for (int k = 0; k < 64; k++) {
            float4 q = *(float4*)&Qs[k*AP + ty*4];
            float4 c = *(float4*)&Ks[k*AP + tx*4];
            sc[0][0] += q.x*c.x; sc[0][1] += q.x*c.y; sc[0][2] += q.x*c.z; sc[0][3] += q.x*c.w;
            sc[1][0] += q.y*c.x; sc[1][1] += q.y*c.y; sc[1][2] += q.y*c.z; sc[1][3] += q.y*c.w;
            sc[2][0] += q.z*c.x; sc[2][1] += q.z*c.y; sc[2][2] += q.z*c.z; sc[2][3] += q.z*c.w;
            sc[3][0] += q.w*c.x; sc[3][1] += q.w*c.y; sc[3][2] += q.w*c.z; sc[3][3] += q.w*c.w;
        }

        // Online softmax. Row r is shared by the 16 threads with equal ty,
        // which sit in an aligned 16-lane half-warp -> shfl_xor 1,2,4,8.
        #pragma unroll
        for (int i = 0; i < 4; i++) {
            float mx = fmaxf(fmaxf(sc[i][0], sc[i][1]), fmaxf(sc[i][2], sc[i][3]));
            mx = fmaxf(mx, __shfl_xor_sync(0xffffffffu, mx, 1));
            mx = fmaxf(mx, __shfl_xor_sync(0xffffffffu, mx, 2));
            mx = fmaxf(mx, __shfl_xor_sync(0xffffffffu, mx, 4));
            mx = fmaxf(mx, __shfl_xor_sync(0xffffffffu, mx, 8));
            float mnew  = fmaxf(mrow[i], mx);
            float alpha = __expf(mrow[i] - mnew);
            mrow[i] = mnew;
            float p0 = __expf(sc[i][0] - mnew);
            float p1 = __expf(sc[i][1] - mnew);
            float p2 = __expf(sc[i][2] - mnew);
            float p3 = __expf(sc[i][3] - mnew);
            float ls = (p0 + p1) + (p2 + p3);
            ls += __shfl_xor_sync(0xffffffffu, ls, 1);
            ls += __shfl_xor_sync(0xffffffffu, ls, 2);
            ls += __shfl_xor_sync(0xffffffffu, ls, 4);
            ls += __shfl_xor_sync(0xffffffffu, ls, 8);
            lrow[i] = lrow[i]*alpha + ls;
            o[i][0] *= alpha; o[i][1] *= alpha; o[i][2] *= alpha; o[i][3] *= alpha;
            sc[i][0] = p0; sc[i][1] = p1; sc[i][2] = p2; sc[i][3] = p3;
        }

        // Write P transposed: Ps[c][r], float4 over the 4 rows this thread owns
        #pragma unroll
        for (int j = 0; j < 4; j++) {
            float4 p = make_float4(sc[0][j], sc[1][j], sc[2][j], sc[3][j]);
            *(float4*)&Ps[(tx*4 + j)*AP + ty*4] = p;
        }
        __syncthreads();   // Ps visible; everyone past Ks reads

        // PV: o[i][j] += sum_c P[r][c] * V[c][d]
        #pragma unroll 4
        for (int c = 0; c < 64; c++) {
            float4 p = *(float4*)&Ps[c*AP + ty*4];
            float4 v = *(float4*)&Vs[c*AP + tx*4];
            o[0][0] += p.x*v.x; o[0][1] += p.x*v.y; o[0][2] += p.x*v.z; o[0][3] += p.x*v.w;
            o[1][0] += p.y*v.x; o[1][1] += p.y*v.y; o[1][2] += p.y*v.z; o[1][3] += p.y*v.w;
            o[2][0] += p.z*v.x; o[2][1] += p.z*v.y; o[2][2] += p.z*v.z; o[2][3] += p.z*v.w;
            o[3][0] += p.w*v.x; o[3][1] += p.w*v.y; o[3][2] += p.w*v.z; o[3][3] += p.w*v.w;
        }
        __syncthreads();   // done reading Vs/Ps before next-iter overwrite
    }

    // Epilogue: out[b][s][h*64 + dd], normalized by row sum
    const int b = bh >> 3, h = bh & 7;
    #pragma unroll
    for (int i = 0; i < 4; i++) {
        float inv = 1.0f / lrow[i];
        int srow = q0 + ty*4 + i;
        float4 r4 = make_float4(o[i][0]*inv, o[i][1]*inv, o[i][2]*inv, o[i][3]*inv);
        *(float4*)&out[(b*SEQ + srow)*HIDDEN + h*HDIM + tx*4] = r4;
    }
}

// ---------------------------------------------------------------------------
extern "C" void kernel_launch(void* const* d_in, const int* in_sizes, int n_in,
                              void* d_out, int out_size)
{
    const float* x = (const float*)d_in[0];      // [2,2048,512]
    const float* W = (const float*)d_in[1];      // [1536,512]
    float* out = (float*)d_out;                  // [2,2048,512]

    dim3 g1(M_TOT/BM, N_TOT/BN);                 // 64 x 24
    qkv_gemm_kernel<<<g1, 256>>>(x, W);

    cudaFuncSetAttribute(attn_kernel,
                         cudaFuncAttributeMaxDynamicSharedMemorySize, ATTN_SMEM);
    dim3 g2(SEQ/64, BATCH*NHEADS);               // 32 x 16
    attn_kernel<<<g2, 256, ATTN_SMEM>>>(out);
}

// round 3
// speedup vs baseline: 2.0829x; 2.0829x over previous
#include <cuda_runtime.h>
#include <cuda_bf16.h>
#include <math.h>
#include <stdint.h>

#define HIDDEN 512
#define NHEADS 8
#define HDIM   64
#define BATCH  2
#define SEQ    2048
#define M_TOT  (BATCH*SEQ)      // 4096
#define N_TOT  (3*HIDDEN)       // 1536
#define K_TOT  HIDDEN           // 512
#define NBH    (BATCH*NHEADS)   // 16

// bf16 hi/lo split Q/K/V, layout [bh][s][d]. Temperature folded into Q.
__device__ __align__(256) __nv_bfloat16 g_Qh[NBH*SEQ*HDIM];
__device__ __align__(256) __nv_bfloat16 g_Ql[NBH*SEQ*HDIM];
__device__ __align__(256) __nv_bfloat16 g_Kh[NBH*SEQ*HDIM];
__device__ __align__(256) __nv_bfloat16 g_Kl[NBH*SEQ*HDIM];
__device__ __align__(256) __nv_bfloat16 g_Vh[NBH*SEQ*HDIM];
__device__ __align__(256) __nv_bfloat16 g_Vl[NBH*SEQ*HDIM];

// ---------------------------------------------------------------------------
// Baseline-PTX helpers (valid at compute_103: no 'a'-features)
// ---------------------------------------------------------------------------
__device__ __forceinline__ uint32_t smem_u32(const void* p) {
    uint32_t a;
    asm("{ .reg .u64 t; cvta.to.shared.u64 t, %1; cvt.u32.u64 %0, t; }"
        : "=r"(a) : "l"(p));
    return a;
}
__device__ __forceinline__ void cpa16(uint32_t s, const void* g) {
    asm volatile("cp.async.cg.shared.global [%0], [%1], 16;"
                 :: "r"(s), "l"(g) : "memory");
}
#define CPA_COMMIT() asm volatile("cp.async.commit_group;" ::: "memory")
#define CPA_WAIT(N)  asm volatile("cp.async.wait_group %0;" :: "n"(N) : "memory")

#define LDMX4(r, a) \
    asm volatile("ldmatrix.sync.aligned.m8n8.x4.shared.b16 {%0,%1,%2,%3}, [%4];" \
                 : "=r"((r)[0]), "=r"((r)[1]), "=r"((r)[2]), "=r"((r)[3]) : "r"(a))
#define LDMX4T(r, a) \
    asm volatile("ldmatrix.sync.aligned.m8n8.x4.trans.shared.b16 {%0,%1,%2,%3}, [%4];" \
                 : "=r"((r)[0]), "=r"((r)[1]), "=r"((r)[2]), "=r"((r)[3]) : "r"(a))

#define MMA(d, a, b0, b1) \
    asm volatile("mma.sync.aligned.m16n8k16.row.col.f32.bf16.bf16.f32 " \
                 "{%0,%1,%2,%3}, {%4,%5,%6,%7}, {%8,%9}, {%0,%1,%2,%3};" \
                 : "+f"((d)[0]), "+f"((d)[1]), "+f"((d)[2]), "+f"((d)[3]) \
                 : "r"((a)[0]), "r"((a)[1]), "r"((a)[2]), "r"((a)[3]), \
                   "r"(b0), "r"(b1))

__device__ __forceinline__ uint32_t pk_bf2(__nv_bfloat16 a, __nv_bfloat16 b) {
    return (uint32_t)__bfloat16_as_ushort(a) | ((uint32_t)__bfloat16_as_ushort(b) << 16);
}

// ---------------------------------------------------------------------------
// QKV GEMM (fp32 SIMT), epilogue -> bf16 hi/lo Q/K/V
// ---------------------------------------------------------------------------
#define BM 64
#define BN 64
#define BK 16
#define GP 68

__global__ __launch_bounds__(256) void qkv_gemm_kernel(
    const float* __restrict__ x, const float* __restrict__ W)
{
    __shared__ float As[BK][GP];
    __shared__ float Bs[BK][GP];

    const int tid = threadIdx.x;
    const int tx = tid & 15;
    const int ty = tid >> 4;
    const int m0 = blockIdx.x * BM;
    const int n0 = blockIdx.y * BN;

    const int lr = tid >> 2;
    const int lk = (tid & 3) * 4;

    float acc[4][4] = {};

    for (int k0 = 0; k0 < K_TOT; k0 += BK) {
        float4 a4 = *(const float4*)&x[(m0 + lr) * K_TOT + k0 + lk];
        float4 b4 = *(const float4*)&W[(n0 + lr) * K_TOT + k0 + lk];
        __syncthreads();
        As[lk+0][lr] = a4.x; As[lk+1][lr] = a4.y;
        As[lk+2][lr] = a4.z; As[lk+3][lr] = a4.w;
        Bs[lk+0][lr] = b4.x; Bs[lk+1][lr] = b4.y;
        Bs[lk+2][lr] = b4.z; Bs[lk+3][lr] = b4.w;
        __syncthreads();
        #pragma unroll
        for (int kk = 0; kk < BK; kk++) {
            float4 av = *(float4*)&As[kk][ty*4];
            float4 bv = *(float4*)&Bs[kk][tx*4];
            acc[0][0] += av.x*bv.x; acc[0][1] += av.x*bv.y;
            acc[0][2] += av.x*bv.z; acc[0][3] += av.x*bv.w;
            acc[1][0] += av.y*bv.x; acc[1][1] += av.y*bv.y;
            acc[1][2] += av.y*bv.z; acc[1][3] += av.y*bv.w;
            acc[2][0] += av.z*bv.x; acc[2][1] += av.z*bv.y;
            acc[2][2] += av.z*bv.z; acc[2][3] += av.z*bv.w;
            acc[3][0] += av.w*bv.x; acc[3][1] += av.w*bv.y;
            acc[3][2] += av.w*bv.z; acc[3][3] += av.w*bv.w;
        }
    }

    // Epilogue: each block's 64 n-cols lie in one 64-wide Q/K/V segment.
    const int n = n0 + tx*4;
    const int h = n / (3*HDIM);
    const int rr = n - h*(3*HDIM);
    const int which = rr >> 6;        // 0=Q 1=K 2=V
    const int dd = rr & 63;
    const float scale = (which == 0) ? 0.125f : 1.0f;  // 1/sqrt(64)

    __nv_bfloat16* dsth = (which == 0) ? g_Qh : (which == 1) ? g_Kh : g_Vh;
    __nv_bfloat16* dstl = (which == 0) ? g_Ql : (which == 1) ? g_Kl : g_Vl;

    #pragma unroll
    for (int i = 0; i < 4; i++) {
        const int m = m0 + ty*4 + i;
        const int b = m >> 11, s = m & (SEQ-1);
        const int bh = b*NHEADS + h;
        __nv_bfloat16 hi[4], lo[4];
        #pragma unroll
        for (int j = 0; j < 4; j++) {
            float v = acc[i][j] * scale;
            hi[j] = __float2bfloat16(v);
            lo[j] = __float2bfloat16(v - __bfloat162float(hi[j]));
        }
        size_t base = ((size_t)bh*SEQ + s)*HDIM + dd;
        *(uint2*)&dsth[base] = make_uint2(pk_bf2(hi[0],hi[1]), pk_bf2(hi[2],hi[3]));
        *(uint2*)&dstl[base] = make_uint2(pk_bf2(lo[0],lo[1]), pk_bf2(lo[2],lo[3]));
    }
}

// ---------------------------------------------------------------------------
// HMMA flash attention. CTA = 64 Q rows x (b,h); 4 warps x 16 rows.
// KV tile 64, cp.async double-buffered. bf16x3 split for both S and PV.
// smem buffers padded to 72 bf16 (144B) per row -> conflict-free ldmatrix.
// ---------------------------------------------------------------------------
#define ROWB 144                     // bytes per smem row
#define BUFB (64*ROWB)               // 9216 bytes per buffer
#define STGB (4*BUFB)                // Kh,Kl,Vh,Vl per stage
#define ATTN_SMEM (2*STGB)           // 73728

__global__ __launch_bounds__(128) void attn_hmma_kernel(float* __restrict__ out)
{
    extern __shared__ char sm[];
    const uint32_t sb = smem_u32(sm);
    const int tid = threadIdx.x;
    const int wid = tid >> 5;
    const int lane = tid & 31;
    const int lq  = lane >> 3;      // ldmatrix quad
    const int lr8 = lane & 7;
    const int g   = lane >> 2;      // mma row group
    const int lam = lane & 3;       // lambda (col pair)
    const int wrow = wid * 16;

    const int bh = blockIdx.y;
    const int q0 = blockIdx.x * 64;
    const int b = bh >> 3, h = bh & 7;

    const __nv_bfloat16* Qhg = g_Qh + (size_t)bh*SEQ*HDIM;
    const __nv_bfloat16* Qlg = g_Ql + (size_t)bh*SEQ*HDIM;
    const __nv_bfloat16* Khg = g_Kh + (size_t)bh*SEQ*HDIM;
    const __nv_bfloat16* Klg = g_Kl + (size_t)bh*SEQ*HDIM;
    const __nv_bfloat16* Vhg = g_Vh + (size_t)bh*SEQ*HDIM;
    const __nv_bfloat16* Vlg = g_Vl + (size_t)bh*SEQ*HDIM;

    // ---- stage Q (hi/lo) through stage-0 buffers 0/1, read into registers ----
    #pragma unroll
    for (int j = 0; j < 4; j++) {
        int c = tid + 128*j;                 // 512 chunks of 16B per buffer
        int row = c >> 3, c8 = c & 7;
        uint32_t so = (uint32_t)(row*ROWB + c8*16);
        cpa16(sb + so,        Qhg + (size_t)(q0+row)*HDIM + c8*8);
        cpa16(sb + BUFB + so, Qlg + (size_t)(q0+row)*HDIM + c8*8);
    }
    CPA_COMMIT();
    CPA_WAIT(0);
    __syncthreads();

    uint32_t QH[4][4], QL[4][4];
    {
        const uint32_t abase = sb + (uint32_t)((wrow + lr8 + (lq&1)*8)*ROWB + ((lq>>1)*8)*2);
        #pragma unroll
        for (int ks = 0; ks < 4; ks++) {
            LDMX4(QH[ks], abase + ks*32);
            LDMX4(QL[ks], abase + BUFB + ks*32);
        }
    }
    __syncthreads();   // everyone done reading stage 0

    // tile-load lambda (stage st, tile base c0)
    auto issue_tile = [&](int st, int c0) {
        const uint32_t s0 = sb + (uint32_t)st * STGB;
        #pragma unroll
        for (int j = 0; j < 4; j++) {
            int c = tid + 128*j;
            int row = c >> 3, c8 = c & 7;
            uint32_t so = (uint32_t)(row*ROWB + c8*16);
            size_t go = (size_t)(c0+row)*HDIM + c8*8;
            cpa16(s0 + so,          Khg + go);
            cpa16(s0 + BUFB + so,   Klg + go);
            cpa16(s0 + 2*BUFB + so, Vhg + go);
            cpa16(s0 + 3*BUFB + so, Vlg + go);
        }
        CPA_COMMIT();
    };

    issue_tile(0, 0);

    float Of[8][4] = {};
    float m0r = -INFINITY, m1r = -INFINITY, l0r = 0.f, l1r = 0.f;

    for (int t = 0; t < SEQ/64; t++) {
        if (t < SEQ/64 - 1) issue_tile((t+1) & 1, (t+1)*64);
        if (t < SEQ/64 - 1) { CPA_WAIT(1); } else { CPA_WAIT(0); }
        __syncthreads();

        const uint32_t s0 = sb + (uint32_t)(t & 1) * STGB;

        // ---- S = Qh*Kh + Qh*Kl + Ql*Kh ----
        float Sf[8][4] = {};
        {
            const uint32_t kb = s0 + (uint32_t)((lr8 + (lq>>1)*8)*ROWB + ((lq&1)*8)*2);
            #pragma unroll
            for (int ks = 0; ks < 4; ks++) {
                #pragma unroll
                for (int np = 0; np < 4; np++) {
                    const uint32_t a = kb + (uint32_t)(np*16*ROWB + ks*32);
                    uint32_t bhf[4], blf[4];
                    LDMX4(bhf, a);
                    LDMX4(blf, a + BUFB);
                    MMA(Sf[2*np],   QH[ks], bhf[0], bhf[1]);
                    MMA(Sf[2*np],   QH[ks], blf[0], blf[1]);
                    MMA(Sf[2*np],   QL[ks], bhf[0], bhf[1]);
                    MMA(Sf[2*np+1], QH[ks], bhf[2], bhf[3]);
                    MMA(Sf[2*np+1], QH[ks], blf[2], blf[3]);
                    MMA(Sf[2*np+1], QL[ks], bhf[2], bhf[3]);
                }
            }
        }

        // ---- online softmax (rows r=wrow+g and r+8; quad-local reductions) ----
        float mx0 = Sf[0][0], mx1 = Sf[0][2];
        #pragma unroll
        for (int nf = 0; nf < 8; nf++) {
            mx0 = fmaxf(mx0, fmaxf(Sf[nf][0], Sf[nf][1]));
            mx1 = fmaxf(mx1, fmaxf(Sf[nf][2], Sf[nf][3]));
        }
        mx0 = fmaxf(mx0, __shfl_xor_sync(0xffffffffu, mx0, 1));
        mx0 = fmaxf(mx0, __shfl_xor_sync(0xffffffffu, mx0, 2));
        mx1 = fmaxf(mx1, __shfl_xor_sync(0xffffffffu, mx1, 1));
        mx1 = fmaxf(mx1, __shfl_xor_sync(0xffffffffu, mx1, 2));
        const float mn0 = fmaxf(m0r, mx0), mn1 = fmaxf(m1r, mx1);
        const float a0 = __expf(m0r - mn0), a1 = __expf(m1r - mn1);
        m0r = mn0; m1r = mn1;

        float rs0 = 0.f, rs1 = 0.f;
        #pragma unroll
        for (int nf = 0; nf < 8; nf++) {
            Sf[nf][0] = __expf(Sf[nf][0] - mn0);
            Sf[nf][1] = __expf(Sf[nf][1] - mn0);
            Sf[nf][2] = __expf(Sf[nf][2] - mn1);
            Sf[nf][3] = __expf(Sf[nf][3] - mn1);
            rs0 += Sf[nf][0] + Sf[nf][1];
            rs1 += Sf[nf][2] + Sf[nf][3];
        }
        rs0 += __shfl_xor_sync(0xffffffffu, rs0, 1);
        rs0 += __shfl_xor_sync(0xffffffffu, rs0, 2);
        rs1 += __shfl_xor_sync(0xffffffffu, rs1, 1);
        rs1 += __shfl_xor_sync(0xffffffffu, rs1, 2);
        l0r = l0r * a0 + rs0;
        l1r = l1r * a1 + rs1;

        #pragma unroll
        for (int nf = 0; nf < 8; nf++) {
            Of[nf][0] *= a0; Of[nf][1] *= a0;
            Of[nf][2] *= a1; Of[nf][3] *= a1;
        }

        // ---- O += Ph*Vh + Pl*Vh + Ph*Vl  (P built from Sf in-register) ----
        {
            const uint32_t vb = s0 + 2*BUFB
                              + (uint32_t)((lr8 + (lq&1)*8)*ROWB + ((lq>>1)*8)*2);
            #pragma unroll
            for (int kc = 0; kc < 4; kc++) {
                uint32_t ah[4], al[4];
                #pragma unroll
                for (int u = 0; u < 2; u++) {      // u=0 -> rows g / u picks frag pair
                    const float* s2 = Sf[2*kc + u];
                    __nv_bfloat16 h0 = __float2bfloat16(s2[0]);
                    __nv_bfloat16 h1 = __float2bfloat16(s2[1]);
                    __nv_bfloat16 h2 = __float2bfloat16(s2[2]);
                    __nv_bfloat16 h3 = __float2bfloat16(s2[3]);
                    ah[2*u]   = pk_bf2(h0, h1);
                    ah[2*u+1] = pk_bf2(h2, h3);
                    al[2*u]   = pk_bf2(__float2bfloat16(s2[0]-__bfloat162float(h0)),
                                       __float2bfloat16(s2[1]-__bfloat162float(h1)));
                    al[2*u+1] = pk_bf2(__float2bfloat16(s2[2]-__bfloat162float(h2)),
                                       __float2bfloat16(s2[3]-__bfloat162float(h3)));
                }
                // frag order fix: A-frag wants {rowsG c0c1 of frag0, rows+8 c2c3 of frag0,
                //                              rowsG c0c1 of frag1, rows+8 c2c3 of frag1}
                // built above as ah = {f0.c01, f0.c23, f1.c01, f1.c23}  ✓
                #pragma unroll
                for (int dp = 0; dp < 4; dp++) {
                    const uint32_t a = vb + (uint32_t)(kc*16*ROWB + dp*32);
                    uint32_t vh[4], vl[4];
                    LDMX4T(vh, a);
                    LDMX4T(vl, a + BUFB);
                    MMA(Of[2*dp],   ah, vh[0], vh[1]);
                    MMA(Of[2*dp],   al, vh[0], vh[1]);
                    MMA(Of[2*dp],   ah, vl[0], vl[1]);
                    MMA(Of[2*dp+1], ah, vh[2], vh[3]);
                    MMA(Of[2*dp+1], al, vh[2], vh[3]);
                    MMA(Of[2*dp+1], ah, vl[2], vl[3]);
                }
            }
        }
        __syncthreads();   // done reading this stage before it is re-issued
    }

    // ---- normalize + store ----
    const float inv0 = 1.0f / l0r, inv1 = 1.0f / l1r;
    const int r0 = q0 + wrow + g;
    float* ob = out + ((size_t)b*SEQ)*HIDDEN + h*HDIM + lam*2;
    #pragma unroll
    for (int nf = 0; nf < 8; nf++) {
        *(float2*)(ob + (size_t)r0*HIDDEN + nf*8) =
            make_float2(Of[nf][0]*inv0, Of[nf][1]*inv0);
        *(float2*)(ob + (size_t)(r0+8)*HIDDEN + nf*8) =
            make_float2(Of[nf][2]*inv1, Of[nf][3]*inv1);
    }
}

// ---------------------------------------------------------------------------
extern "C" void kernel_launch(void* const* d_in, const int* in_sizes, int n_in,
                              void* d_out, int out_size)
{
    const float* x = (const float*)d_in[0];
    const float* W = (const float*)d_in[1];
    float* out = (float*)d_out;

    dim3 g1(M_TOT/BM, N_TOT/BN);
    qkv_gemm_kernel<<<g1, 256>>>(x, W);

    cudaFuncSetAttribute(attn_hmma_kernel,
                         cudaFuncAttributeMaxDynamicSharedMemorySize, ATTN_SMEM);
    dim3 g2(SEQ/64, NBH);
    attn_hmma_kernel<<<g2, 128, ATTN_SMEM>>>(out);
}

// round 4
// speedup vs baseline: 2.9870x; 1.4341x over previous
#include <cuda_runtime.h>
#include <cuda_bf16.h>
#include <math.h>
#include <stdint.h>

#define HIDDEN 512
#define NHEADS 8
#define HDIM   64
#define BATCH  2
#define SEQ    2048
#define M_TOT  (BATCH*SEQ)      // 4096
#define N_TOT  (3*HIDDEN)       // 1536
#define K_TOT  HIDDEN           // 512
#define NBH    (BATCH*NHEADS)   // 16

// bf16 hi/lo split Q/K/V, layout [bh][s][d]. Temperature folded into Q.
__device__ __align__(256) __nv_bfloat16 g_Qh[NBH*SEQ*HDIM];
__device__ __align__(256) __nv_bfloat16 g_Ql[NBH*SEQ*HDIM];
__device__ __align__(256) __nv_bfloat16 g_Kh[NBH*SEQ*HDIM];
__device__ __align__(256) __nv_bfloat16 g_Kl[NBH*SEQ*HDIM];
__device__ __align__(256) __nv_bfloat16 g_Vh[NBH*SEQ*HDIM];
__device__ __align__(256) __nv_bfloat16 g_Vl[NBH*SEQ*HDIM];

// bf16 hi/lo split inputs for the HMMA QKV GEMM
__device__ __align__(256) __nv_bfloat16 g_xh[M_TOT*K_TOT];
__device__ __align__(256) __nv_bfloat16 g_xl[M_TOT*K_TOT];
__device__ __align__(256) __nv_bfloat16 g_wh[N_TOT*K_TOT];
__device__ __align__(256) __nv_bfloat16 g_wl[N_TOT*K_TOT];

// ---------------------------------------------------------------------------
// Baseline-PTX helpers (valid at compute_103: no 'a'-features)
// ---------------------------------------------------------------------------
__device__ __forceinline__ uint32_t smem_u32(const void* p) {
    uint32_t a;
    asm("{ .reg .u64 t; cvta.to.shared.u64 t, %1; cvt.u32.u64 %0, t; }"
        : "=r"(a) : "l"(p));
    return a;
}
__device__ __forceinline__ void cpa16(uint32_t s, const void* g) {
    asm volatile("cp.async.cg.shared.global [%0], [%1], 16;"
                 :: "r"(s), "l"(g) : "memory");
}
#define CPA_COMMIT() asm volatile("cp.async.commit_group;" ::: "memory")
#define CPA_WAIT(N)  asm volatile("cp.async.wait_group %0;" :: "n"(N) : "memory")

#define LDMX4(r, a) \
    asm volatile("ldmatrix.sync.aligned.m8n8.x4.shared.b16 {%0,%1,%2,%3}, [%4];" \
                 : "=r"((r)[0]), "=r"((r)[1]), "=r"((r)[2]), "=r"((r)[3]) : "r"(a))
#define LDMX4T(r, a) \
    asm volatile("ldmatrix.sync.aligned.m8n8.x4.trans.shared.b16 {%0,%1,%2,%3}, [%4];" \
                 : "=r"((r)[0]), "=r"((r)[1]), "=r"((r)[2]), "=r"((r)[3]) : "r"(a))

#define MMA(d, a, b0, b1) \
    asm volatile("mma.sync.aligned.m16n8k16.row.col.f32.bf16.bf16.f32 " \
                 "{%0,%1,%2,%3}, {%4,%5,%6,%7}, {%8,%9}, {%0,%1,%2,%3};" \
                 : "+f"((d)[0]), "+f"((d)[1]), "+f"((d)[2]), "+f"((d)[3]) \
                 : "r"((a)[0]), "r"((a)[1]), "r"((a)[2]), "r"((a)[3]), \
                   "r"(b0), "r"(b1))

__device__ __forceinline__ uint32_t pk_bf2(__nv_bfloat16 a, __nv_bfloat16 b) {
    return (uint32_t)__bfloat16_as_ushort(a) | ((uint32_t)__bfloat16_as_ushort(b) << 16);
}

// ---------------------------------------------------------------------------
// Split kernel: fp32 x / W -> bf16 hi/lo arrays
// ---------------------------------------------------------------------------
#define XV4   (M_TOT*K_TOT/4)      // 524288 float4s for x
#define WV4   (N_TOT*K_TOT/4)      // 196608 float4s for W
#define SPLIT_THREADS 256
#define SPLIT_BLOCKS  ((XV4 + WV4 + SPLIT_THREADS - 1) / SPLIT_THREADS)

__global__ __launch_bounds__(SPLIT_THREADS) void split_kernel(
    const float* __restrict__ x, const float* __restrict__ W)
{
    const int i = blockIdx.x * SPLIT_THREADS + threadIdx.x;
    const float4* src;
    __nv_bfloat16 *dh, *dl;
    int idx;
    if (i < XV4) {
        src = (const float4*)x; dh = g_xh; dl = g_xl; idx = i;
    } else if (i < XV4 + WV4) {
        src = (const float4*)W; dh = g_wh; dl = g_wl; idx = i - XV4;
    } else return;

    float4 v = src[idx];
    __nv_bfloat16 h0 = __float2bfloat16(v.x), h1 = __float2bfloat16(v.y);
    __nv_bfloat16 h2 = __float2bfloat16(v.z), h3 = __float2bfloat16(v.w);
    uint2 hv = make_uint2(pk_bf2(h0,h1), pk_bf2(h2,h3));
    uint2 lv = make_uint2(
        pk_bf2(__float2bfloat16(v.x-__bfloat162float(h0)),
               __float2bfloat16(v.y-__bfloat162float(h1))),
        pk_bf2(__float2bfloat16(v.z-__bfloat162float(h2)),
               __float2bfloat16(v.w-__bfloat162float(h3))));
    *(uint2*)&dh[idx*4] = hv;
    *(uint2*)&dl[idx*4] = lv;
}

// ---------------------------------------------------------------------------
// HMMA QKV GEMM: C[m][n] = sum_k x[m][k]*W[n][k], bf16x3 split.
// CTA = 128 m-rows x 64 n-cols, 8 warps x 16 rows. K chunk 64, 2-stage cp.async.
// Epilogue splits C into bf16 hi/lo Q/K/V (temperature folded into Q).
// ---------------------------------------------------------------------------
#define GROWB 144
#define GBUF_A (128*GROWB)            // 18432
#define GBUF_B (64*GROWB)             // 9216
#define GOFF_AH 0
#define GOFF_AL GBUF_A
#define GOFF_BH (2*GBUF_A)
#define GOFF_BL (2*GBUF_A + GBUF_B)
#define GSTG   (2*GBUF_A + 2*GBUF_B)  // 55296
#define GEMM_SMEM (2*GSTG)            // 110592

__global__ __launch_bounds__(256) void qkv_hmma_kernel()
{
    extern __shared__ char sm[];
    const uint32_t sb = smem_u32(sm);
    const int tid = threadIdx.x;
    const int wid = tid >> 5;
    const int lane = tid & 31;
    const int lq  = lane >> 3;
    const int lr8 = lane & 7;
    const int g   = lane >> 2;
    const int lam = lane & 3;
    const int wrow = wid * 16;

    const int m0 = blockIdx.x * 128;
    const int n0 = blockIdx.y * 64;

    auto issue_tile = [&](int st, int k0) {
        const uint32_t s0 = sb + (uint32_t)st * GSTG;
        // A: 1024 16B-chunks per buffer (128 rows x 8)
        #pragma unroll
        for (int j = 0; j < 4; j++) {
            int c = tid + 256*j;
            int row = c >> 3, c8 = c & 7;
            uint32_t so = (uint32_t)(row*GROWB + c8*16);
            size_t go = (size_t)(m0+row)*K_TOT + k0 + c8*8;
            cpa16(s0 + GOFF_AH + so, g_xh + go);
            cpa16(s0 + GOFF_AL + so, g_xl + go);
        }
        // B: 512 16B-chunks per buffer (64 rows x 8)
        #pragma unroll
        for (int j = 0; j < 2; j++) {
            int c = tid + 256*j;
            int row = c >> 3, c8 = c & 7;
            uint32_t so = (uint32_t)(row*GROWB + c8*16);
            size_t go = (size_t)(n0+row)*K_TOT + k0 + c8*8;
            cpa16(s0 + GOFF_BH + so, g_wh + go);
            cpa16(s0 + GOFF_BL + so, g_wl + go);
        }
        CPA_COMMIT();
    };

    issue_tile(0, 0);

    float Cf[8][4] = {};

    for (int t = 0; t < K_TOT/64; t++) {
        if (t < K_TOT/64 - 1) issue_tile((t+1) & 1, (t+1)*64);
        if (t < K_TOT/64 - 1) { CPA_WAIT(1); } else { CPA_WAIT(0); }
        __syncthreads();

        const uint32_t s0 = sb + (uint32_t)(t & 1) * GSTG;
        const uint32_t abase = s0 + GOFF_AH
                             + (uint32_t)((wrow + lr8 + (lq&1)*8)*GROWB + ((lq>>1)*8)*2);
        const uint32_t kb = s0 + GOFF_BH
                          + (uint32_t)((lr8 + (lq>>1)*8)*GROWB + ((lq&1)*8)*2);

        #pragma unroll
        for (int ks = 0; ks < 4; ks++) {
            uint32_t aH[4], aL[4];
            LDMX4(aH, abase + ks*32);
            LDMX4(aL, abase + (GOFF_AL - GOFF_AH) + ks*32);
            #pragma unroll
            for (int np = 0; np < 4; np++) {
                const uint32_t a = kb + (uint32_t)(np*16*GROWB + ks*32);
                uint32_t bhf[4], blf[4];
                LDMX4(bhf, a);
                LDMX4(blf, a + (GOFF_BL - GOFF_BH));
                MMA(Cf[2*np],   aH, bhf[0], bhf[1]);
                MMA(Cf[2*np],   aH, blf[0], blf[1]);
                MMA(Cf[2*np],   aL, bhf[0], bhf[1]);
                MMA(Cf[2*np+1], aH, bhf[2], bhf[3]);
                MMA(Cf[2*np+1], aH, blf[2], blf[3]);
                MMA(Cf[2*np+1], aL, bhf[2], bhf[3]);
            }
        }
        __syncthreads();
    }

    // Epilogue: this CTA's 64 n-cols are one (h, which) segment.
    const int h = n0 / (3*HDIM);
    const int rr = n0 - h*(3*HDIM);
    const int which = rr >> 6;        // 0=Q 1=K 2=V
    const float scale = (which == 0) ? 0.125f : 1.0f;
    __nv_bfloat16* dsth = (which == 0) ? g_Qh : (which == 1) ? g_Kh : g_Vh;
    __nv_bfloat16* dstl = (which == 0) ? g_Ql : (which == 1) ? g_Kl : g_Vl;

    const int m_a = m0 + wrow + g;
    const int b_a = m_a >> 11, s_a = m_a & (SEQ-1);
    const int m_b = m_a + 8;
    const int b_b = m_b >> 11, s_b = m_b & (SEQ-1);
    const size_t base_a = ((size_t)(b_a*NHEADS + h)*SEQ + s_a)*HDIM;
    const size_t base_b = ((size_t)(b_b*NHEADS + h)*SEQ + s_b)*HDIM;

    #pragma unroll
    for (int nf = 0; nf < 8; nf++) {
        const int dd = nf*8 + lam*2;
        float v0 = Cf[nf][0]*scale, v1 = Cf[nf][1]*scale;
        float v2 = Cf[nf][2]*scale, v3 = Cf[nf][3]*scale;
        __nv_bfloat16 h0 = __float2bfloat16(v0), h1 = __float2bfloat16(v1);
        __nv_bfloat16 h2 = __float2bfloat16(v2), h3 = __float2bfloat16(v3);
        *(uint32_t*)&dsth[base_a + dd] = pk_bf2(h0, h1);
        *(uint32_t*)&dstl[base_a + dd] = pk_bf2(
            __float2bfloat16(v0-__bfloat162float(h0)),
            __float2bfloat16(v1-__bfloat162float(h1)));
        *(uint32_t*)&dsth[base_b + dd] = pk_bf2(h2, h3);
        *(uint32_t*)&dstl[base_b + dd] = pk_bf2(
            __float2bfloat16(v2-__bfloat162float(h2)),
            __float2bfloat16(v3-__bfloat162float(h3)));
    }
}

// ---------------------------------------------------------------------------
// HMMA flash attention (unchanged from round 3).
// ---------------------------------------------------------------------------
#define ROWB 144
#define BUFB (64*ROWB)
#define STGB (4*BUFB)
#define ATTN_SMEM (2*STGB)

__global__ __launch_bounds__(128) void attn_hmma_kernel(float* __restrict__ out)
{
    extern __shared__ char sm[];
    const uint32_t sb = smem_u32(sm);
    const int tid = threadIdx.x;
    const int wid = tid >> 5;
    const int lane = tid & 31;
    const int lq  = lane >> 3;
    const int lr8 = lane & 7;
    const int g   = lane >> 2;
    const int lam = lane & 3;
    const int wrow = wid * 16;

    const int bh = blockIdx.y;
    const int q0 = blockIdx.x * 64;
    const int b = bh >> 3, h = bh & 7;

    const __nv_bfloat16* Qhg = g_Qh + (size_t)bh*SEQ*HDIM;
    const __nv_bfloat16* Qlg = g_Ql + (size_t)bh*SEQ*HDIM;
    const __nv_bfloat16* Khg = g_Kh + (size_t)bh*SEQ*HDIM;
    const __nv_bfloat16* Klg = g_Kl + (size_t)bh*SEQ*HDIM;
    const __nv_bfloat16* Vhg = g_Vh + (size_t)bh*SEQ*HDIM;
    const __nv_bfloat16* Vlg = g_Vl + (size_t)bh*SEQ*HDIM;

    #pragma unroll
    for (int j = 0; j < 4; j++) {
        int c = tid + 128*j;
        int row = c >> 3, c8 = c & 7;
        uint32_t so = (uint32_t)(row*ROWB + c8*16);
        cpa16(sb + so,        Qhg + (size_t)(q0+row)*HDIM + c8*8);
        cpa16(sb + BUFB + so, Qlg + (size_t)(q0+row)*HDIM + c8*8);
    }
    CPA_COMMIT();
    CPA_WAIT(0);
    __syncthreads();

    uint32_t QH[4][4], QL[4][4];
    {
        const uint32_t abase = sb + (uint32_t)((wrow + lr8 + (lq&1)*8)*ROWB + ((lq>>1)*8)*2);
        #pragma unroll
        for (int ks = 0; ks < 4; ks++) {
            LDMX4(QH[ks], abase + ks*32);
            LDMX4(QL[ks], abase + BUFB + ks*32);
        }
    }
    __syncthreads();

    auto issue_tile = [&](int st, int c0) {
        const uint32_t s0 = sb + (uint32_t)st * STGB;
        #pragma unroll
        for (int j = 0; j < 4; j++) {
            int c = tid + 128*j;
            int row = c >> 3, c8 = c & 7;
            uint32_t so = (uint32_t)(row*ROWB + c8*16);
            size_t go = (size_t)(c0+row)*HDIM + c8*8;
            cpa16(s0 + so,          Khg + go);
            cpa16(s0 + BUFB + so,   Klg + go);
            cpa16(s0 + 2*BUFB + so, Vhg + go);
            cpa16(s0 + 3*BUFB + so, Vlg + go);
        }
        CPA_COMMIT();
    };

    issue_tile(0, 0);

    float Of[8][4] = {};
    float m0r = -INFINITY, m1r = -INFINITY, l0r = 0.f, l1r = 0.f;

    for (int t = 0; t < SEQ/64; t++) {
        if (t < SEQ/64 - 1) issue_tile((t+1) & 1, (t+1)*64);
        if (t < SEQ/64 - 1) { CPA_WAIT(1); } else { CPA_WAIT(0); }
        __syncthreads();

        const uint32_t s0 = sb + (uint32_t)(t & 1) * STGB;

        float Sf[8][4] = {};
        {
            const uint32_t kb = s0 + (uint32_t)((lr8 + (lq>>1)*8)*ROWB + ((lq&1)*8)*2);
            #pragma unroll
            for (int ks = 0; ks < 4; ks++) {
                #pragma unroll
                for (int np = 0; np < 4; np++) {
                    const uint32_t a = kb + (uint32_t)(np*16*ROWB + ks*32);
                    uint32_t bhf[4], blf[4];
                    LDMX4(bhf, a);
                    LDMX4(blf, a + BUFB);
                    MMA(Sf[2*np],   QH[ks], bhf[0], bhf[1]);
                    MMA(Sf[2*np],   QH[ks], blf[0], blf[1]);
                    MMA(Sf[2*np],   QL[ks], bhf[0], bhf[1]);
                    MMA(Sf[2*np+1], QH[ks], bhf[2], bhf[3]);
                    MMA(Sf[2*np+1], QH[ks], blf[2], blf[3]);
                    MMA(Sf[2*np+1], QL[ks], bhf[2], bhf[3]);
                }
            }
        }

        float mx0 = Sf[0][0], mx1 = Sf[0][2];
        #pragma unroll
        for (int nf = 0; nf < 8; nf++) {
            mx0 = fmaxf(mx0, fmaxf(Sf[nf][0], Sf[nf][1]));
            mx1 = fmaxf(mx1, fmaxf(Sf[nf][2], Sf[nf][3]));
        }
        mx0 = fmaxf(mx0, __shfl_xor_sync(0xffffffffu, mx0, 1));
        mx0 = fmaxf(mx0, __shfl_xor_sync(0xffffffffu, mx0, 2));
        mx1 = fmaxf(mx1, __shfl_xor_sync(0xffffffffu, mx1, 1));
        mx1 = fmaxf(mx1, __shfl_xor_sync(0xffffffffu, mx1, 2));
        const float mn0 = fmaxf(m0r, mx0), mn1 = fmaxf(m1r, mx1);
        const float a0 = __expf(m0r - mn0), a1 = __expf(m1r - mn1);
        m0r = mn0; m1r = mn1;

        float rs0 = 0.f, rs1 = 0.f;
        #pragma unroll
        for (int nf = 0; nf < 8; nf++) {
            Sf[nf][0] = __expf(Sf[nf][0] - mn0);
            Sf[nf][1] = __expf(Sf[nf][1] - mn0);
            Sf[nf][2] = __expf(Sf[nf][2] - mn1);
            Sf[nf][3] = __expf(Sf[nf][3] - mn1);
            rs0 += Sf[nf][0] + Sf[nf][1];
            rs1 += Sf[nf][2] + Sf[nf][3];
        }
        rs0 += __shfl_xor_sync(0xffffffffu, rs0, 1);
        rs0 += __shfl_xor_sync(0xffffffffu, rs0, 2);
        rs1 += __shfl_xor_sync(0xffffffffu, rs1, 1);
        rs1 += __shfl_xor_sync(0xffffffffu, rs1, 2);
        l0r = l0r * a0 + rs0;
        l1r = l1r * a1 + rs1;

        #pragma unroll
        for (int nf = 0; nf < 8; nf++) {
            Of[nf][0] *= a0; Of[nf][1] *= a0;
            Of[nf][2] *= a1; Of[nf][3] *= a1;
        }

        {
            const uint32_t vb = s0 + 2*BUFB
                              + (uint32_t)((lr8 + (lq&1)*8)*ROWB + ((lq>>1)*8)*2);
            #pragma unroll
            for (int kc = 0; kc < 4; kc++) {
                uint32_t ah[4], al[4];
                #pragma unroll
                for (int u = 0; u < 2; u++) {
                    const float* s2 = Sf[2*kc + u];
                    __nv_bfloat16 h0 = __float2bfloat16(s2[0]);
                    __nv_bfloat16 h1 = __float2bfloat16(s2[1]);
                    __nv_bfloat16 h2 = __float2bfloat16(s2[2]);
                    __nv_bfloat16 h3 = __float2bfloat16(s2[3]);
                    ah[2*u]   = pk_bf2(h0, h1);
                    ah[2*u+1] = pk_bf2(h2, h3);
                    al[2*u]   = pk_bf2(__float2bfloat16(s2[0]-__bfloat162float(h0)),
                                       __float2bfloat16(s2[1]-__bfloat162float(h1)));
                    al[2*u+1] = pk_bf2(__float2bfloat16(s2[2]-__bfloat162float(h2)),
                                       __float2bfloat16(s2[3]-__bfloat162float(h3)));
                }
                #pragma unroll
                for (int dp = 0; dp < 4; dp++) {
                    const uint32_t a = vb + (uint32_t)(kc*16*ROWB + dp*32);
                    uint32_t vh[4], vl[4];
                    LDMX4T(vh, a);
                    LDMX4T(vl, a + BUFB);
                    MMA(Of[2*dp],   ah, vh[0], vh[1]);
                    MMA(Of[2*dp],   al, vh[0], vh[1]);
                    MMA(Of[2*dp],   ah, vl[0], vl[1]);
                    MMA(Of[2*dp+1], ah, vh[2], vh[3]);
                    MMA(Of[2*dp+1], al, vh[2], vh[3]);
                    MMA(Of[2*dp+1], ah, vl[2], vl[3]);
                }
            }
        }
        __syncthreads();
    }

    const float inv0 = 1.0f / l0r, inv1 = 1.0f / l1r;
    const int r0 = q0 + wrow + g;
    float* ob = out + ((size_t)b*SEQ)*HIDDEN + h*HDIM + lam*2;
    #pragma unroll
    for (int nf = 0; nf < 8; nf++) {
        *(float2*)(ob + (size_t)r0*HIDDEN + nf*8) =
            make_float2(Of[nf][0]*inv0, Of[nf][1]*inv0);
        *(float2*)(ob + (size_t)(r0+8)*HIDDEN + nf*8) =
            make_float2(Of[nf][2]*inv1, Of[nf][3]*inv1);
    }
}

// ---------------------------------------------------------------------------
extern "C" void kernel_launch(void* const* d_in, const int* in_sizes, int n_in,
                              void* d_out, int out_size)
{
    const float* x = (const float*)d_in[0];
    const float* W = (const float*)d_in[1];
    float* out = (float*)d_out;

    split_kernel<<<SPLIT_BLOCKS, SPLIT_THREADS>>>(x, W);

    cudaFuncSetAttribute(qkv_hmma_kernel,
                         cudaFuncAttributeMaxDynamicSharedMemorySize, GEMM_SMEM);
    dim3 g1(M_TOT/128, N_TOT/64);
    qkv_hmma_kernel<<<g1, 256, GEMM_SMEM>>>();

    cudaFuncSetAttribute(attn_hmma_kernel,
                         cudaFuncAttributeMaxDynamicSharedMemorySize, ATTN_SMEM);
    dim3 g2(SEQ/64, NBH);
    attn_hmma_kernel<<<g2, 128, ATTN_SMEM>>>(out);
}

// round 5
// speedup vs baseline: 3.8692x; 1.2954x over previous
#include <cuda_runtime.h>
#include <cuda_fp16.h>
#include <math.h>
#include <stdint.h>

#define HIDDEN 512
#define NHEADS 8
#define HDIM   64
#define BATCH  2
#define SEQ    2048
#define M_TOT  (BATCH*SEQ)      // 4096
#define N_TOT  (3*HIDDEN)       // 1536
#define K_TOT  HIDDEN           // 512
#define NBH    (BATCH*NHEADS)   // 16

// fp16 tensors. Q single (temperature folded), K/V hi+lo split, layout [bh][s][d].
__device__ __align__(256) __half g_Q [NBH*SEQ*HDIM];
__device__ __align__(256) __half g_Kh[NBH*SEQ*HDIM];
__device__ __align__(256) __half g_Kl[NBH*SEQ*HDIM];
__device__ __align__(256) __half g_Vh[NBH*SEQ*HDIM];
__device__ __align__(256) __half g_Vl[NBH*SEQ*HDIM];

// fp16 GEMM inputs: x single, W hi+lo (pre-scaled by 16 to keep lo normal).
__device__ __align__(256) __half g_xh[M_TOT*K_TOT];
__device__ __align__(256) __half g_wh[N_TOT*K_TOT];
__device__ __align__(256) __half g_wl[N_TOT*K_TOT];

// ---------------------------------------------------------------------------
// Baseline-PTX helpers (valid at compute_103: no 'a'-features)
// ---------------------------------------------------------------------------
__device__ __forceinline__ uint32_t smem_u32(const void* p) {
    uint32_t a;
    asm("{ .reg .u64 t; cvta.to.shared.u64 t, %1; cvt.u32.u64 %0, t; }"
        : "=r"(a) : "l"(p));
    return a;
}
__device__ __forceinline__ void cpa16(uint32_t s, const void* g) {
    asm volatile("cp.async.cg.shared.global [%0], [%1], 16;"
                 :: "r"(s), "l"(g) : "memory");
}
#define CPA_COMMIT() asm volatile("cp.async.commit_group;" ::: "memory")
#define CPA_WAIT(N)  asm volatile("cp.async.wait_group %0;" :: "n"(N) : "memory")

#define LDMX4(r, a) \
    asm volatile("ldmatrix.sync.aligned.m8n8.x4.shared.b16 {%0,%1,%2,%3}, [%4];" \
                 : "=r"((r)[0]), "=r"((r)[1]), "=r"((r)[2]), "=r"((r)[3]) : "r"(a))
#define LDMX4T(r, a) \
    asm volatile("ldmatrix.sync.aligned.m8n8.x4.trans.shared.b16 {%0,%1,%2,%3}, [%4];" \
                 : "=r"((r)[0]), "=r"((r)[1]), "=r"((r)[2]), "=r"((r)[3]) : "r"(a))

#define MMA(d, a, b0, b1) \
    asm volatile("mma.sync.aligned.m16n8k16.row.col.f32.f16.f16.f32 " \
                 "{%0,%1,%2,%3}, {%4,%5,%6,%7}, {%8,%9}, {%0,%1,%2,%3};" \
                 : "+f"((d)[0]), "+f"((d)[1]), "+f"((d)[2]), "+f"((d)[3]) \
                 : "r"((a)[0]), "r"((a)[1]), "r"((a)[2]), "r"((a)[3]), \
                   "r"(b0), "r"(b1))

__device__ __forceinline__ uint32_t pk_h2(__half a, __half b) {
    return (uint32_t)__half_as_ushort(a) | ((uint32_t)__half_as_ushort(b) << 16);
}

#define WSCALE 16.0f
#define WINV   (1.0f/16.0f)

// ---------------------------------------------------------------------------
// Split kernel: fp32 x -> fp16 x; fp32 W -> fp16 hi/lo (x16 scale)
// ---------------------------------------------------------------------------
#define XV4   (M_TOT*K_TOT/4)
#define WV4   (N_TOT*K_TOT/4)
#define SPLIT_THREADS 256
#define SPLIT_BLOCKS  ((XV4 + WV4 + SPLIT_THREADS - 1) / SPLIT_THREADS)

__global__ __launch_bounds__(SPLIT_THREADS) void split_kernel(
    const float* __restrict__ x, const float* __restrict__ W)
{
    const int i = blockIdx.x * SPLIT_THREADS + threadIdx.x;
    if (i < XV4) {
        float4 v = ((const float4*)x)[i];
        *(uint2*)&g_xh[i*4] = make_uint2(
            pk_h2(__float2half_rn(v.x), __float2half_rn(v.y)),
            pk_h2(__float2half_rn(v.z), __float2half_rn(v.w)));
    } else if (i < XV4 + WV4) {
        int idx = i - XV4;
        float4 v = ((const float4*)W)[idx];
        v.x *= WSCALE; v.y *= WSCALE; v.z *= WSCALE; v.w *= WSCALE;
        __half h0 = __float2half_rn(v.x), h1 = __float2half_rn(v.y);
        __half h2 = __float2half_rn(v.z), h3 = __float2half_rn(v.w);
        *(uint2*)&g_wh[idx*4] = make_uint2(pk_h2(h0,h1), pk_h2(h2,h3));
        *(uint2*)&g_wl[idx*4] = make_uint2(
            pk_h2(__float2half_rn(v.x-__half2float(h0)),
                  __float2half_rn(v.y-__half2float(h1))),
            pk_h2(__float2half_rn(v.z-__half2float(h2)),
                  __float2half_rn(v.w-__half2float(h3))));
    }
}

// ---------------------------------------------------------------------------
// HMMA QKV GEMM (fp16 2-term): C = x_h16 * (Wh + Wl)^T / 16.
// CTA = 128 m x 64 n, 8 warps. K chunk 64, 2-stage cp.async.
// ---------------------------------------------------------------------------
#define GROWB 144
#define GBUF_A (128*GROWB)            // 18432
#define GBUF_B (64*GROWB)             // 9216
#define GOFF_A  0
#define GOFF_BH GBUF_A
#define GOFF_BL (GBUF_A + GBUF_B)
#define GSTG    (GBUF_A + 2*GBUF_B)   // 36864
#define GEMM_SMEM (2*GSTG)            // 73728

__global__ __launch_bounds__(256) void qkv_hmma_kernel()
{
    extern __shared__ char sm[];
    const uint32_t sb = smem_u32(sm);
    const int tid = threadIdx.x;
    const int wid = tid >> 5;
    const int lane = tid & 31;
    const int lq  = lane >> 3;
    const int lr8 = lane & 7;
    const int g   = lane >> 2;
    const int lam = lane & 3;
    const int wrow = wid * 16;

    const int m0 = blockIdx.x * 128;
    const int n0 = blockIdx.y * 64;

    auto issue_tile = [&](int st, int k0) {
        const uint32_t s0 = sb + (uint32_t)st * GSTG;
        #pragma unroll
        for (int j = 0; j < 4; j++) {           // A: 1024 chunks
            int c = tid + 256*j;
            int row = c >> 3, c8 = c & 7;
            uint32_t so = (uint32_t)(row*GROWB + c8*16);
            cpa16(s0 + GOFF_A + so, g_xh + (size_t)(m0+row)*K_TOT + k0 + c8*8);
        }
        #pragma unroll
        for (int j = 0; j < 2; j++) {           // B: 512 chunks each
            int c = tid + 256*j;
            int row = c >> 3, c8 = c & 7;
            uint32_t so = (uint32_t)(row*GROWB + c8*16);
            size_t go = (size_t)(n0+row)*K_TOT + k0 + c8*8;
            cpa16(s0 + GOFF_BH + so, g_wh + go);
            cpa16(s0 + GOFF_BL + so, g_wl + go);
        }
        CPA_COMMIT();
    };

    issue_tile(0, 0);

    float Cf[8][4] = {};

    for (int t = 0; t < K_TOT/64; t++) {
        if (t < K_TOT/64 - 1) issue_tile((t+1) & 1, (t+1)*64);
        if (t < K_TOT/64 - 1) { CPA_WAIT(1); } else { CPA_WAIT(0); }
        __syncthreads();

        const uint32_t s0 = sb + (uint32_t)(t & 1) * GSTG;
        const uint32_t abase = s0 + GOFF_A
                             + (uint32_t)((wrow + lr8 + (lq&1)*8)*GROWB + ((lq>>1)*8)*2);
        const uint32_t kb = s0 + GOFF_BH
                          + (uint32_t)((lr8 + (lq>>1)*8)*GROWB + ((lq&1)*8)*2);

        #pragma unroll
        for (int ks = 0; ks < 4; ks++) {
            uint32_t aF[4];
            LDMX4(aF, abase + ks*32);
            #pragma unroll
            for (int np = 0; np < 4; np++) {
                const uint32_t a = kb + (uint32_t)(np*16*GROWB + ks*32);
                uint32_t bhf[4], blf[4];
                LDMX4(bhf, a);
                LDMX4(blf, a + (GOFF_BL - GOFF_BH));
                MMA(Cf[2*np],   aF, bhf[0], bhf[1]);
                MMA(Cf[2*np],   aF, blf[0], blf[1]);
                MMA(Cf[2*np+1], aF, bhf[2], bhf[3]);
                MMA(Cf[2*np+1], aF, blf[2], blf[3]);
            }
        }
        __syncthreads();
    }

    // Epilogue: this CTA's 64 n-cols are one (h, which) segment.
    const int h = n0 / (3*HDIM);
    const int rr = n0 - h*(3*HDIM);
    const int which = rr >> 6;        // 0=Q 1=K 2=V
    const float scale = ((which == 0) ? 0.125f : 1.0f) * WINV;

    const int m_a = m0 + wrow + g;
    const int b_a = m_a >> 11, s_a = m_a & (SEQ-1);
    const int m_b = m_a + 8;
    const int b_b = m_b >> 11, s_b = m_b & (SEQ-1);
    const size_t base_a = ((size_t)(b_a*NHEADS + h)*SEQ + s_a)*HDIM;
    const size_t base_b = ((size_t)(b_b*NHEADS + h)*SEQ + s_b)*HDIM;

    __half* dsth = (which == 0) ? g_Q : (which == 1) ? g_Kh : g_Vh;
    __half* dstl = (which == 1) ? g_Kl : g_Vl;   // unused for Q

    #pragma unroll
    for (int nf = 0; nf < 8; nf++) {
        const int dd = nf*8 + lam*2;
        float v0 = Cf[nf][0]*scale, v1 = Cf[nf][1]*scale;
        float v2 = Cf[nf][2]*scale, v3 = Cf[nf][3]*scale;
        __half h0 = __float2half_rn(v0), h1 = __float2half_rn(v1);
        __half h2 = __float2half_rn(v2), h3 = __float2half_rn(v3);
        *(uint32_t*)&dsth[base_a + dd] = pk_h2(h0, h1);
        *(uint32_t*)&dsth[base_b + dd] = pk_h2(h2, h3);
        if (which != 0) {
            *(uint32_t*)&dstl[base_a + dd] = pk_h2(
                __float2half_rn(v0-__half2float(h0)),
                __float2half_rn(v1-__half2float(h1)));
            *(uint32_t*)&dstl[base_b + dd] = pk_h2(
                __float2half_rn(v2-__half2float(h2)),
                __float2half_rn(v3-__half2float(h3)));
        }
    }
}

// ---------------------------------------------------------------------------
// HMMA flash attention, fp16 2-term: S = Q̂·(Kh+Kl), O += P̂·(Vh+Vl).
// CTA = 64 Q rows x (b,h); 4 warps x 16 rows; KV tile 64, 2-stage cp.async.
// ---------------------------------------------------------------------------
#define ROWB 144
#define BUFB (64*ROWB)
#define STGB (4*BUFB)                 // Kh,Kl,Vh,Vl
#define ATTN_SMEM (2*STGB)            // 73728

__global__ __launch_bounds__(128) void attn_hmma_kernel(float* __restrict__ out)
{
    extern __shared__ char sm[];
    const uint32_t sb = smem_u32(sm);
    const int tid = threadIdx.x;
    const int lane = tid & 31;
    const int wid = tid >> 5;
    const int lq  = lane >> 3;
    const int lr8 = lane & 7;
    const int g   = lane >> 2;
    const int lam = lane & 3;
    const int wrow = wid * 16;

    const int bh = blockIdx.y;
    const int q0 = blockIdx.x * 64;
    const int b = bh >> 3, h = bh & 7;

    const __half* Qg  = g_Q  + (size_t)bh*SEQ*HDIM;
    const __half* Khg = g_Kh + (size_t)bh*SEQ*HDIM;
    const __half* Klg = g_Kl + (size_t)bh*SEQ*HDIM;
    const __half* Vhg = g_Vh + (size_t)bh*SEQ*HDIM;
    const __half* Vlg = g_Vl + (size_t)bh*SEQ*HDIM;

    // Stage Q through stage-0 buffer 0, read frags, then reuse the buffer.
    #pragma unroll
    for (int j = 0; j < 4; j++) {
        int c = tid + 128*j;
        int row = c >> 3, c8 = c & 7;
        cpa16(sb + (uint32_t)(row*ROWB + c8*16),
              Qg + (size_t)(q0+row)*HDIM + c8*8);
    }
    CPA_COMMIT();
    CPA_WAIT(0);
    __syncthreads();

    uint32_t QF[4][4];
    {
        const uint32_t abase = sb + (uint32_t)((wrow + lr8 + (lq&1)*8)*ROWB + ((lq>>1)*8)*2);
        #pragma unroll
        for (int ks = 0; ks < 4; ks++) LDMX4(QF[ks], abase + ks*32);
    }
    __syncthreads();

    auto issue_tile = [&](int st, int c0) {
        const uint32_t s0 = sb + (uint32_t)st * STGB;
        #pragma unroll
        for (int j = 0; j < 4; j++) {
            int c = tid + 128*j;
            int row = c >> 3, c8 = c & 7;
            uint32_t so = (uint32_t)(row*ROWB + c8*16);
            size_t go = (size_t)(c0+row)*HDIM + c8*8;
            cpa16(s0 + so,          Khg + go);
            cpa16(s0 + BUFB + so,   Klg + go);
            cpa16(s0 + 2*BUFB + so, Vhg + go);
            cpa16(s0 + 3*BUFB + so, Vlg + go);
        }
        CPA_COMMIT();
    };

    issue_tile(0, 0);

    float Of[8][4] = {};
    float m0r = -INFINITY, m1r = -INFINITY, l0r = 0.f, l1r = 0.f;

    for (int t = 0; t < SEQ/64; t++) {
        if (t < SEQ/64 - 1) issue_tile((t+1) & 1, (t+1)*64);
        if (t < SEQ/64 - 1) { CPA_WAIT(1); } else { CPA_WAIT(0); }
        __syncthreads();

        const uint32_t s0 = sb + (uint32_t)(t & 1) * STGB;

        // ---- S = Q̂·Kh + Q̂·Kl ----
        float Sf[8][4] = {};
        {
            const uint32_t kb = s0 + (uint32_t)((lr8 + (lq>>1)*8)*ROWB + ((lq&1)*8)*2);
            #pragma unroll
            for (int ks = 0; ks < 4; ks++) {
                #pragma unroll
                for (int np = 0; np < 4; np++) {
                    const uint32_t a = kb + (uint32_t)(np*16*ROWB + ks*32);
                    uint32_t bhf[4], blf[4];
                    LDMX4(bhf, a);
                    LDMX4(blf, a + BUFB);
                    MMA(Sf[2*np],   QF[ks], bhf[0], bhf[1]);
                    MMA(Sf[2*np],   QF[ks], blf[0], blf[1]);
                    MMA(Sf[2*np+1], QF[ks], bhf[2], bhf[3]);
                    MMA(Sf[2*np+1], QF[ks], blf[2], blf[3]);
                }
            }
        }

        // ---- online softmax ----
        float mx0 = Sf[0][0], mx1 = Sf[0][2];
        #pragma unroll
        for (int nf = 0; nf < 8; nf++) {
            mx0 = fmaxf(mx0, fmaxf(Sf[nf][0], Sf[nf][1]));
            mx1 = fmaxf(mx1, fmaxf(Sf[nf][2], Sf[nf][3]));
        }
        mx0 = fmaxf(mx0, __shfl_xor_sync(0xffffffffu, mx0, 1));
        mx0 = fmaxf(mx0, __shfl_xor_sync(0xffffffffu, mx0, 2));
        mx1 = fmaxf(mx1, __shfl_xor_sync(0xffffffffu, mx1, 1));
        mx1 = fmaxf(mx1, __shfl_xor_sync(0xffffffffu, mx1, 2));
        const float mn0 = fmaxf(m0r, mx0), mn1 = fmaxf(m1r, mx1);
        const float a0 = __expf(m0r - mn0), a1 = __expf(m1r - mn1);
        m0r = mn0; m1r = mn1;

        float rs0 = 0.f, rs1 = 0.f;
        #pragma unroll
        for (int nf = 0; nf < 8; nf++) {
            Sf[nf][0] = __expf(Sf[nf][0] - mn0);
            Sf[nf][1] = __expf(Sf[nf][1] - mn0);
            Sf[nf][2] = __expf(Sf[nf][2] - mn1);
            Sf[nf][3] = __expf(Sf[nf][3] - mn1);
            rs0 += Sf[nf][0] + Sf[nf][1];
            rs1 += Sf[nf][2] + Sf[nf][3];
        }
        rs0 += __shfl_xor_sync(0xffffffffu, rs0, 1);
        rs0 += __shfl_xor_sync(0xffffffffu, rs0, 2);
        rs1 += __shfl_xor_sync(0xffffffffu, rs1, 1);
        rs1 += __shfl_xor_sync(0xffffffffu, rs1, 2);
        l0r = l0r * a0 + rs0;
        l1r = l1r * a1 + rs1;

        #pragma unroll
        for (int nf = 0; nf < 8; nf++) {
            Of[nf][0] *= a0; Of[nf][1] *= a0;
            Of[nf][2] *= a1; Of[nf][3] *= a1;
        }

        // ---- O += P̂·Vh + P̂·Vl ----
        {
            const uint32_t vb = s0 + 2*BUFB
                              + (uint32_t)((lr8 + (lq&1)*8)*ROWB + ((lq>>1)*8)*2);
            #pragma unroll
            for (int kc = 0; kc < 4; kc++) {
                uint32_t ah[4];
                #pragma unroll
                for (int u = 0; u < 2; u++) {
                    const float* s2 = Sf[2*kc + u];
                    ah[2*u]   = pk_h2(__float2half_rn(s2[0]), __float2half_rn(s2[1]));
                    ah[2*u+1] = pk_h2(__float2half_rn(s2[2]), __float2half_rn(s2[3]));
                }
                #pragma unroll
                for (int dp = 0; dp < 4; dp++) {
                    const uint32_t a = vb + (uint32_t)(kc*16*ROWB + dp*32);
                    uint32_t vh[4], vl[4];
                    LDMX4T(vh, a);
                    LDMX4T(vl, a + BUFB);
                    MMA(Of[2*dp],   ah, vh[0], vh[1]);
                    MMA(Of[2*dp],   ah, vl[0], vl[1]);
                    MMA(Of[2*dp+1], ah, vh[2], vh[3]);
                    MMA(Of[2*dp+1], ah, vl[2], vl[3]);
                }
            }
        }
        __syncthreads();
    }

    const float inv0 = 1.0f / l0r, inv1 = 1.0f / l1r;
    const int r0 = q0 + wrow + g;
    float* ob = out + ((size_t)b*SEQ)*HIDDEN + h*HDIM + lam*2;
    #pragma unroll
    for (int nf = 0; nf < 8; nf++) {
        *(float2*)(ob + (size_t)r0*HIDDEN + nf*8) =
            make_float2(Of[nf][0]*inv0, Of[nf][1]*inv0);
        *(float2*)(ob + (size_t)(r0+8)*HIDDEN + nf*8) =
            make_float2(Of[nf][2]*inv1, Of[nf][3]*inv1);
    }
}

// ---------------------------------------------------------------------------
extern "C" void kernel_launch(void* const* d_in, const int* in_sizes, int n_in,
                              void* d_out, int out_size)
{
    const float* x = (const float*)d_in[0];
    const float* W = (const float*)d_in[1];
    float* out = (float*)d_out;

    split_kernel<<<SPLIT_BLOCKS, SPLIT_THREADS>>>(x, W);

    cudaFuncSetAttribute(qkv_hmma_kernel,
                         cudaFuncAttributeMaxDynamicSharedMemorySize, GEMM_SMEM);
    dim3 g1(M_TOT/128, N_TOT/64);
    qkv_hmma_kernel<<<g1, 256, GEMM_SMEM>>>();

    cudaFuncSetAttribute(attn_hmma_kernel,
                         cudaFuncAttributeMaxDynamicSharedMemorySize, ATTN_SMEM);
    dim3 g2(SEQ/64, NBH);
    attn_hmma_kernel<<<g2, 128, ATTN_SMEM>>>(out);
}

// round 6
// speedup vs baseline: 6.9590x; 1.7986x over previous
#include <cuda_runtime.h>
#include <cuda_fp16.h>
#include <math.h>
#include <stdint.h>

#define HIDDEN 512
#define NHEADS 8
#define HDIM   64
#define BATCH  2
#define SEQ    2048
#define M_TOT  (BATCH*SEQ)      // 4096
#define N_TOT  (3*HIDDEN)       // 1536
#define K_TOT  HIDDEN           // 512
#define NBH    (BATCH*NHEADS)   // 16

// fp16 tensors, layout [bh][s][d]. Temperature folded into Q.
__device__ __align__(256) __half g_Q[NBH*SEQ*HDIM];
__device__ __align__(256) __half g_K[NBH*SEQ*HDIM];
__device__ __align__(256) __half g_V[NBH*SEQ*HDIM];

// fp16 GEMM inputs
__device__ __align__(256) __half g_xh[M_TOT*K_TOT];
__device__ __align__(256) __half g_wh[N_TOT*K_TOT];

// ---------------------------------------------------------------------------
// Baseline-PTX helpers (valid at compute_103: no 'a'-features)
// ---------------------------------------------------------------------------
__device__ __forceinline__ uint32_t smem_u32(const void* p) {
    uint32_t a;
    asm("{ .reg .u64 t; cvta.to.shared.u64 t, %1; cvt.u32.u64 %0, t; }"
        : "=r"(a) : "l"(p));
    return a;
}
__device__ __forceinline__ void cpa16(uint32_t s, const void* g) {
    asm volatile("cp.async.cg.shared.global [%0], [%1], 16;"
                 :: "r"(s), "l"(g) : "memory");
}
#define CPA_COMMIT() asm volatile("cp.async.commit_group;" ::: "memory")
#define CPA_WAIT(N)  asm volatile("cp.async.wait_group %0;" :: "n"(N) : "memory")

#define LDMX4(r, a) \
    asm volatile("ldmatrix.sync.aligned.m8n8.x4.shared.b16 {%0,%1,%2,%3}, [%4];" \
                 : "=r"((r)[0]), "=r"((r)[1]), "=r"((r)[2]), "=r"((r)[3]) : "r"(a))
#define LDMX4T(r, a) \
    asm volatile("ldmatrix.sync.aligned.m8n8.x4.trans.shared.b16 {%0,%1,%2,%3}, [%4];" \
                 : "=r"((r)[0]), "=r"((r)[1]), "=r"((r)[2]), "=r"((r)[3]) : "r"(a))

#define MMA(d, a, b0, b1) \
    asm volatile("mma.sync.aligned.m16n8k16.row.col.f32.f16.f16.f32 " \
                 "{%0,%1,%2,%3}, {%4,%5,%6,%7}, {%8,%9}, {%0,%1,%2,%3};" \
                 : "+f"((d)[0]), "+f"((d)[1]), "+f"((d)[2]), "+f"((d)[3]) \
                 : "r"((a)[0]), "r"((a)[1]), "r"((a)[2]), "r"((a)[3]), \
                   "r"(b0), "r"(b1))

__device__ __forceinline__ uint32_t pk_h2(__half a, __half b) {
    return (uint32_t)__half_as_ushort(a) | ((uint32_t)__half_as_ushort(b) << 16);
}

// ---------------------------------------------------------------------------
// Split kernel: fp32 x / W -> fp16
// ---------------------------------------------------------------------------
#define XV4   (M_TOT*K_TOT/4)
#define WV4   (N_TOT*K_TOT/4)
#define SPLIT_THREADS 256
#define SPLIT_BLOCKS  ((XV4 + WV4 + SPLIT_THREADS - 1) / SPLIT_THREADS)

__global__ __launch_bounds__(SPLIT_THREADS) void split_kernel(
    const float* __restrict__ x, const float* __restrict__ W)
{
    const int i = blockIdx.x * SPLIT_THREADS + threadIdx.x;
    const float4* src;
    __half* dst;
    int idx;
    if (i < XV4)            { src = (const float4*)x; dst = g_xh; idx = i; }
    else if (i < XV4 + WV4) { src = (const float4*)W; dst = g_wh; idx = i - XV4; }
    else return;

    float4 v = src[idx];
    *(uint2*)&dst[idx*4] = make_uint2(
        pk_h2(__float2half_rn(v.x), __float2half_rn(v.y)),
        pk_h2(__float2half_rn(v.z), __float2half_rn(v.w)));
}

// ---------------------------------------------------------------------------
// HMMA QKV GEMM (fp16 single): C = x̂ * Ŵ^T.
// CTA = 128 m x 64 n, 8 warps. K chunk 64, 2-stage cp.async.
// ---------------------------------------------------------------------------
#define GROWB 144
#define GBUF_A (128*GROWB)            // 18432
#define GBUF_B (64*GROWB)             // 9216
#define GOFF_A  0
#define GOFF_B  GBUF_A
#define GSTG    (GBUF_A + GBUF_B)     // 27648
#define GEMM_SMEM (2*GSTG)            // 55296

__global__ __launch_bounds__(256) void qkv_hmma_kernel()
{
    extern __shared__ char sm[];
    const uint32_t sb = smem_u32(sm);
    const int tid = threadIdx.x;
    const int wid = tid >> 5;
    const int lane = tid & 31;
    const int lq  = lane >> 3;
    const int lr8 = lane & 7;
    const int g   = lane >> 2;
    const int lam = lane & 3;
    const int wrow = wid * 16;

    const int m0 = blockIdx.x * 128;
    const int n0 = blockIdx.y * 64;

    auto issue_tile = [&](int st, int k0) {
        const uint32_t s0 = sb + (uint32_t)st * GSTG;
        #pragma unroll
        for (int j = 0; j < 4; j++) {           // A: 1024 chunks
            int c = tid + 256*j;
            int row = c >> 3, c8 = c & 7;
            cpa16(s0 + GOFF_A + (uint32_t)(row*GROWB + c8*16),
                  g_xh + (size_t)(m0+row)*K_TOT + k0 + c8*8);
        }
        #pragma unroll
        for (int j = 0; j < 2; j++) {           // B: 512 chunks
            int c = tid + 256*j;
            int row = c >> 3, c8 = c & 7;
            cpa16(s0 + GOFF_B + (uint32_t)(row*GROWB + c8*16),
                  g_wh + (size_t)(n0+row)*K_TOT + k0 + c8*8);
        }
        CPA_COMMIT();
    };

    issue_tile(0, 0);

    float Cf[8][4] = {};

    for (int t = 0; t < K_TOT/64; t++) {
        if (t < K_TOT/64 - 1) issue_tile((t+1) & 1, (t+1)*64);
        if (t < K_TOT/64 - 1) { CPA_WAIT(1); } else { CPA_WAIT(0); }
        __syncthreads();

        const uint32_t s0 = sb + (uint32_t)(t & 1) * GSTG;
        const uint32_t abase = s0 + GOFF_A
                             + (uint32_t)((wrow + lr8 + (lq&1)*8)*GROWB + ((lq>>1)*8)*2);
        const uint32_t kb = s0 + GOFF_B
                          + (uint32_t)((lr8 + (lq>>1)*8)*GROWB + ((lq&1)*8)*2);

        #pragma unroll
        for (int ks = 0; ks < 4; ks++) {
            uint32_t aF[4];
            LDMX4(aF, abase + ks*32);
            #pragma unroll
            for (int np = 0; np < 4; np++) {
                uint32_t bf[4];
                LDMX4(bf, kb + (uint32_t)(np*16*GROWB + ks*32));
                MMA(Cf[2*np],   aF, bf[0], bf[1]);
                MMA(Cf[2*np+1], aF, bf[2], bf[3]);
            }
        }
        __syncthreads();
    }

    // Epilogue: this CTA's 64 n-cols are one (h, which) segment.
    const int h = n0 / (3*HDIM);
    const int rr = n0 - h*(3*HDIM);
    const int which = rr >> 6;        // 0=Q 1=K 2=V
    const float scale = (which == 0) ? 0.125f : 1.0f;
    __half* dst = (which == 0) ? g_Q : (which == 1) ? g_K : g_V;

    const int m_a = m0 + wrow + g;
    const int b_a = m_a >> 11, s_a = m_a & (SEQ-1);
    const int m_b = m_a + 8;
    const int b_b = m_b >> 11, s_b = m_b & (SEQ-1);
    const size_t base_a = ((size_t)(b_a*NHEADS + h)*SEQ + s_a)*HDIM;
    const size_t base_b = ((size_t)(b_b*NHEADS + h)*SEQ + s_b)*HDIM;

    #pragma unroll
    for (int nf = 0; nf < 8; nf++) {
        const int dd = nf*8 + lam*2;
        *(uint32_t*)&dst[base_a + dd] = pk_h2(
            __float2half_rn(Cf[nf][0]*scale), __float2half_rn(Cf[nf][1]*scale));
        *(uint32_t*)&dst[base_b + dd] = pk_h2(
            __float2half_rn(Cf[nf][2]*scale), __float2half_rn(Cf[nf][3]*scale));
    }
}

// ---------------------------------------------------------------------------
// HMMA flash attention, fp16 single: S = Q̂·K̂, O += P̂·V̂.
// CTA = 64 Q rows x (b,h); 4 warps x 16 rows; KV tile 64, 2-stage cp.async.
// ---------------------------------------------------------------------------
#define ROWB 144
#define BUFB (64*ROWB)                // 9216
#define STGB (2*BUFB)                 // K, V
#define ATTN_SMEM (2*STGB)            // 36864

__global__ __launch_bounds__(128) void attn_hmma_kernel(float* __restrict__ out)
{
    extern __shared__ char sm[];
    const uint32_t sb = smem_u32(sm);
    const int tid = threadIdx.x;
    const int lane = tid & 31;
    const int wid = tid >> 5;
    const int lq  = lane >> 3;
    const int lr8 = lane & 7;
    const int g   = lane >> 2;
    const int lam = lane & 3;
    const int wrow = wid * 16;

    const int bh = blockIdx.y;
    const int q0 = blockIdx.x * 64;
    const int b = bh >> 3, h = bh & 7;

    const __half* Qg = g_Q + (size_t)bh*SEQ*HDIM;
    const __half* Kg = g_K + (size_t)bh*SEQ*HDIM;
    const __half* Vg = g_V + (size_t)bh*SEQ*HDIM;

    // Stage Q through stage-0 K buffer, read frags, then reuse the buffer.
    #pragma unroll
    for (int j = 0; j < 4; j++) {
        int c = tid + 128*j;
        int row = c >> 3, c8 = c & 7;
        cpa16(sb + (uint32_t)(row*ROWB + c8*16),
              Qg + (size_t)(q0+row)*HDIM + c8*8);
    }
    CPA_COMMIT();
    CPA_WAIT(0);
    __syncthreads();

    uint32_t QF[4][4];
    {
        const uint32_t abase = sb + (uint32_t)((wrow + lr8 + (lq&1)*8)*ROWB + ((lq>>1)*8)*2);
        #pragma unroll
        for (int ks = 0; ks < 4; ks++) LDMX4(QF[ks], abase + ks*32);
    }
    __syncthreads();

    auto issue_tile = [&](int st, int c0) {
        const uint32_t s0 = sb + (uint32_t)st * STGB;
        #pragma unroll
        for (int j = 0; j < 4; j++) {
            int c = tid + 128*j;
            int row = c >> 3, c8 = c & 7;
            uint32_t so = (uint32_t)(row*ROWB + c8*16);
            size_t go = (size_t)(c0+row)*HDIM + c8*8;
            cpa16(s0 + so,        Kg + go);
            cpa16(s0 + BUFB + so, Vg + go);
        }
        CPA_COMMIT();
    };

    issue_tile(0, 0);

    float Of[8][4] = {};
    float m0r = -INFINITY, m1r = -INFINITY, l0r = 0.f, l1r = 0.f;

    for (int t = 0; t < SEQ/64; t++) {
        if (t < SEQ/64 - 1) issue_tile((t+1) & 1, (t+1)*64);
        if (t < SEQ/64 - 1) { CPA_WAIT(1); } else { CPA_WAIT(0); }
        __syncthreads();

        const uint32_t s0 = sb + (uint32_t)(t & 1) * STGB;

        // ---- S = Q̂·K̂ ----
        float Sf[8][4] = {};
        {
            const uint32_t kb = s0 + (uint32_t)((lr8 + (lq>>1)*8)*ROWB + ((lq&1)*8)*2);
            #pragma unroll
            for (int ks = 0; ks < 4; ks++) {
                #pragma unroll
                for (int np = 0; np < 4; np++) {
                    uint32_t bf[4];
                    LDMX4(bf, kb + (uint32_t)(np*16*ROWB + ks*32));
                    MMA(Sf[2*np],   QF[ks], bf[0], bf[1]);
                    MMA(Sf[2*np+1], QF[ks], bf[2], bf[3]);
                }
            }
        }

        // ---- online softmax ----
        float mx0 = Sf[0][0], mx1 = Sf[0][2];
        #pragma unroll
        for (int nf = 0; nf < 8; nf++) {
            mx0 = fmaxf(mx0, fmaxf(Sf[nf][0], Sf[nf][1]));
            mx1 = fmaxf(mx1, fmaxf(Sf[nf][2], Sf[nf][3]));
        }
        mx0 = fmaxf(mx0, __shfl_xor_sync(0xffffffffu, mx0, 1));
        mx0 = fmaxf(mx0, __shfl_xor_sync(0xffffffffu, mx0, 2));
        mx1 = fmaxf(mx1, __shfl_xor_sync(0xffffffffu, mx1, 1));
        mx1 = fmaxf(mx1, __shfl_xor_sync(0xffffffffu, mx1, 2));
        const float mn0 = fmaxf(m0r, mx0), mn1 = fmaxf(m1r, mx1);
        const float a0 = __expf(m0r - mn0), a1 = __expf(m1r - mn1);
        m0r = mn0; m1r = mn1;

        float rs0 = 0.f, rs1 = 0.f;
        #pragma unroll
        for (int nf = 0; nf < 8; nf++) {
            Sf[nf][0] = __expf(Sf[nf][0] - mn0);
            Sf[nf][1] = __expf(Sf[nf][1] - mn0);
            Sf[nf][2] = __expf(Sf[nf][2] - mn1);
            Sf[nf][3] = __expf(Sf[nf][3] - mn1);
            rs0 += Sf[nf][0] + Sf[nf][1];
            rs1 += Sf[nf][2] + Sf[nf][3];
        }
        rs0 += __shfl_xor_sync(0xffffffffu, rs0, 1);
        rs0 += __shfl_xor_sync(0xffffffffu, rs0, 2);
        rs1 += __shfl_xor_sync(0xffffffffu, rs1, 1);
        rs1 += __shfl_xor_sync(0xffffffffu, rs1, 2);
        l0r = l0r * a0 + rs0;
        l1r = l1r * a1 + rs1;

        #pragma unroll
        for (int nf = 0; nf < 8; nf++) {
            Of[nf][0] *= a0; Of[nf][1] *= a0;
            Of[nf][2] *= a1; Of[nf][3] *= a1;
        }

        // ---- O += P̂·V̂ ----
        {
            const uint32_t vb = s0 + BUFB
                              + (uint32_t)((lr8 + (lq&1)*8)*ROWB + ((lq>>1)*8)*2);
            #pragma unroll
            for (int kc = 0; kc < 4; kc++) {
                uint32_t ah[4];
                #pragma unroll
                for (int u = 0; u < 2; u++) {
                    const float* s2 = Sf[2*kc + u];
                    ah[2*u]   = pk_h2(__float2half_rn(s2[0]), __float2half_rn(s2[1]));
                    ah[2*u+1] = pk_h2(__float2half_rn(s2[2]), __float2half_rn(s2[3]));
                }
                #pragma unroll
                for (int dp = 0; dp < 4; dp++) {
                    uint32_t vf[4];
                    LDMX4T(vf, vb + (uint32_t)(kc*16*ROWB + dp*32));
                    MMA(Of[2*dp],   ah, vf[0], vf[1]);
                    MMA(Of[2*dp+1], ah, vf[2], vf[3]);
                }
            }
        }
        __syncthreads();
    }

    const float inv0 = 1.0f / l0r, inv1 = 1.0f / l1r;
    const int r0 = q0 + wrow + g;
    float* ob = out + ((size_t)b*SEQ)*HIDDEN + h*HDIM + lam*2;
    #pragma unroll
    for (int nf = 0; nf < 8; nf++) {
        *(float2*)(ob + (size_t)r0*HIDDEN + nf*8) =
            make_float2(Of[nf][0]*inv0, Of[nf][1]*inv0);
        *(float2*)(ob + (size_t)(r0+8)*HIDDEN + nf*8) =
            make_float2(Of[nf][2]*inv1, Of[nf][3]*inv1);
    }
}

// ---------------------------------------------------------------------------
extern "C" void kernel_launch(void* const* d_in, const int* in_sizes, int n_in,
                              void* d_out, int out_size)
{
    const float* x = (const float*)d_in[0];
    const float* W = (const float*)d_in[1];
    float* out = (float*)d_out;

    split_kernel<<<SPLIT_BLOCKS, SPLIT_THREADS>>>(x, W);

    cudaFuncSetAttribute(qkv_hmma_kernel,
                         cudaFuncAttributeMaxDynamicSharedMemorySize, GEMM_SMEM);
    dim3 g1(M_TOT/128, N_TOT/64);
    qkv_hmma_kernel<<<g1, 256, GEMM_SMEM>>>();

    cudaFuncSetAttribute(attn_hmma_kernel,
                         cudaFuncAttributeMaxDynamicSharedMemorySize, ATTN_SMEM);
    dim3 g2(SEQ/64, NBH);
    attn_hmma_kernel<<<g2, 128, ATTN_SMEM>>>(out);
}